// round 3
// baseline (speedup 1.0000x reference)
#include <cuda_runtime.h>
#include <math.h>

#define Bn 16384
#define Dn 1024
#define Hn 4096
#define MAXK 72
#define MAXA 544

// ---- output layout (elements, fp32) ----
static const size_t OFF_LATK   = 0ULL;
static const size_t OFF_XB     = (size_t)Bn * Hn;                 // 67108864
static const size_t OFF_PREM2  = OFF_XB + (size_t)Bn * Dn;        // 83886080
static const size_t OFF_LAT4K  = OFF_PREM2 + (size_t)Bn * Hn;     // 150994944
static const size_t OFF_LATAUX = OFF_LAT4K + (size_t)Bn * Hn;     // 218103808
static const size_t OFF_RECK   = OFF_LATAUX + (size_t)Bn * Hn;    // 285212672
static const size_t OFF_REC4K  = OFF_RECK + (size_t)Bn * Dn;      // 301989888
static const size_t OFF_RECAUX = OFF_REC4K + (size_t)Bn * Dn;     // 318767104
static const size_t OFF_RECKPB = OFF_RECAUX + (size_t)Bn * Dn;    // 335544320
static const size_t OFF_STATS  = OFF_RECKPB + (size_t)Bn * Dn;    // 352321536

// ---- device scratch (static; no allocations) ----
__device__ float    g_pre[(size_t)Bn * Hn];       // 256 MB
__device__ int      g_hits1[Hn];
__device__ int      g_hits2[Hn];
__device__ int      g_stats1[Hn];
__device__ unsigned g_dead1[Hn / 32];
__device__ unsigned g_dead12[Hn / 32];
__device__ int      g_kcnt[Bn];
__device__ int      g_kidx[(size_t)Bn * MAXK];
__device__ float    g_kval[(size_t)Bn * MAXK];
__device__ int      g_acnt[Bn];
__device__ int      g_aidx[(size_t)Bn * MAXA];
__device__ float    g_aval[(size_t)Bn * MAXA];

// monotone key: larger key <=> larger float
__device__ __forceinline__ unsigned fkey(float f) {
    unsigned u = __float_as_uint(f);
    return (u & 0x80000000u) ? ~u : (u | 0x80000000u);
}

// ---------------------------------------------------------------------------
// init: zero hit flags (must re-zero every launch; graph replays)
// ---------------------------------------------------------------------------
__global__ void k_init() {
    int i = blockIdx.x * 256 + threadIdx.x;
    if (i < Hn) { g_hits1[i] = 0; g_hits2[i] = 0; }
}

// ---------------------------------------------------------------------------
// xb = x - pre_bias  (written to output, reused as GEMM input)
// ---------------------------------------------------------------------------
__global__ void k_xb(const float* __restrict__ x, const float* __restrict__ pb,
                     float* __restrict__ out) {
    size_t i = (size_t)blockIdx.x * 256 + threadIdx.x;   // over Bn*Dn/4
    int c4 = (int)(i & (Dn / 4 - 1));
    float4 xv = ((const float4*)x)[i];
    float4 bv = ((const float4*)pb)[c4];
    float4 o;
    o.x = xv.x - bv.x; o.y = xv.y - bv.y; o.z = xv.z - bv.z; o.w = xv.w - bv.w;
    ((float4*)out)[i] = o;
}

// ---------------------------------------------------------------------------
// encode GEMM: pre[b][h] = dot(xb[b,:], W[h,:]) + latent_bias[h]   (fp32)
// 128x128x16 block tile, 256 threads, 8x8 per thread
// ---------------------------------------------------------------------------
#define BM 128
#define BN 128
#define BK 16

__global__ __launch_bounds__(256, 2)
void k_gemm(const float* __restrict__ A,   // [Bn, Dn] xb
            const float* __restrict__ Bw,  // [Hn, Dn] enc_weight
            const float* __restrict__ bias) {
    __shared__ __align__(16) float As[BK][BM];
    __shared__ __align__(16) float Bs[BK][BN];

    const int tid  = threadIdx.x;
    const int brow = blockIdx.y * BM;
    const int bcol = blockIdx.x * BN;
    const int ty = tid >> 4, tx = tid & 15;

    const float* Arow = A  + (size_t)brow * Dn;
    const float* Brow = Bw + (size_t)bcol * Dn;

    float acc[8][8];
#pragma unroll
    for (int i = 0; i < 8; i++)
#pragma unroll
        for (int j = 0; j < 8; j++) acc[i][j] = 0.f;

    for (int k0 = 0; k0 < Dn; k0 += BK) {
#pragma unroll
        for (int l = 0; l < 2; l++) {
            int f  = tid + l * 256;      // float4 index 0..511
            int rr = f >> 2;             // row in tile
            int kq = f & 3;              // which float4 of the 16-K slab
            float4 va = *(const float4*)(Arow + (size_t)rr * Dn + k0 + kq * 4);
            As[kq * 4 + 0][rr] = va.x; As[kq * 4 + 1][rr] = va.y;
            As[kq * 4 + 2][rr] = va.z; As[kq * 4 + 3][rr] = va.w;
            float4 vb = *(const float4*)(Brow + (size_t)rr * Dn + k0 + kq * 4);
            Bs[kq * 4 + 0][rr] = vb.x; Bs[kq * 4 + 1][rr] = vb.y;
            Bs[kq * 4 + 2][rr] = vb.z; Bs[kq * 4 + 3][rr] = vb.w;
        }
        __syncthreads();

#pragma unroll
        for (int kk = 0; kk < BK; kk++) {
            float4 a0 = *(const float4*)&As[kk][ty * 8];
            float4 a1 = *(const float4*)&As[kk][ty * 8 + 4];
            float4 b0 = *(const float4*)&Bs[kk][tx * 8];
            float4 b1 = *(const float4*)&Bs[kk][tx * 8 + 4];
            float a[8] = {a0.x, a0.y, a0.z, a0.w, a1.x, a1.y, a1.z, a1.w};
            float b[8] = {b0.x, b0.y, b0.z, b0.w, b1.x, b1.y, b1.z, b1.w};
#pragma unroll
            for (int i = 0; i < 8; i++)
#pragma unroll
                for (int j = 0; j < 8; j++) acc[i][j] += a[i] * b[j];
        }
        __syncthreads();
    }

#pragma unroll
    for (int i = 0; i < 8; i++) {
        size_t r = (size_t)(brow + ty * 8 + i);
#pragma unroll
        for (int j = 0; j < 8; j += 4) {
            int c = bcol + tx * 8 + j;
            float4 o;
            o.x = acc[i][j + 0] + bias[c + 0];
            o.y = acc[i][j + 1] + bias[c + 1];
            o.z = acc[i][j + 2] + bias[c + 2];
            o.w = acc[i][j + 3] + bias[c + 3];
            *(float4*)(g_pre + r * Hn + c) = o;
        }
    }
}

// ---------------------------------------------------------------------------
// per-row radix select (k-th largest key among 4096 smem-resident keys)
// ---------------------------------------------------------------------------
struct SelShared {
    float    sv[Hn];
    unsigned su[Hn];
    int      hist[256];
    int      scan[256];
    int      bbin;
    int      bkk;
    int      cnt;
};

__device__ unsigned radix_kth(SelShared* s, int k) {
    const int tid = threadIdx.x;
    unsigned prefix = 0, mask = 0;
    int kk = k;
#pragma unroll
    for (int shift = 24; shift >= 0; shift -= 8) {
        s->hist[tid] = 0;
        __syncthreads();
        for (int i = tid; i < Hn; i += 256) {
            unsigned u = s->su[i];
            if ((u & mask) == prefix) atomicAdd(&s->hist[(u >> shift) & 255], 1);
        }
        __syncthreads();
        s->scan[tid] = s->hist[tid];
        __syncthreads();
        for (int off = 1; off < 256; off <<= 1) {
            int add = (tid + off < 256) ? s->scan[tid + off] : 0;
            __syncthreads();
            s->scan[tid] += add;
            __syncthreads();
        }
        int ge = s->scan[tid];
        int gt = (tid < 255) ? s->scan[tid + 1] : 0;
        if (ge >= kk && gt < kk) { s->bbin = tid; s->bkk = kk - gt; }
        __syncthreads();
        prefix |= ((unsigned)s->bbin) << shift;
        mask   |= 0xFFu << shift;
        kk = s->bkk;
        __syncthreads();
    }
    return prefix;
}

// ---------------------------------------------------------------------------
// top-64 on pre: lat_k out, hits1, compact (idx,val) list
// ---------------------------------------------------------------------------
__global__ void k_sel64(float* __restrict__ latk) {
    __shared__ SelShared s;
    const int r = blockIdx.x, tid = threadIdx.x;
    const float* row = g_pre + (size_t)r * Hn;
    for (int i = tid; i < Hn; i += 256) {
        float v = row[i];
        s.sv[i] = v;
        s.su[i] = fkey(v);
    }
    if (tid == 0) s.cnt = 0;
    __syncthreads();
    unsigned t64 = radix_kth(&s, 64);
    float* orow = latk + (size_t)r * Hn;
    for (int i = tid; i < Hn; i += 256) {
        float v = s.sv[i];
        bool sel = (s.su[i] >= t64);
        orow[i] = sel ? fmaxf(v, 0.f) : 0.f;
        if (sel) {
            if (v > 1e-5f) g_hits1[i] = 1;
            if (v > 0.f) {
                int p = atomicAdd(&s.cnt, 1);
                if (p < MAXK) {
                    g_kidx[(size_t)r * MAXK + p] = i;
                    g_kval[(size_t)r * MAXK + p] = v;
                }
            }
        }
    }
    __syncthreads();
    if (tid == 0) g_kcnt[r] = (s.cnt < MAXK) ? s.cnt : MAXK;
}

// ---------------------------------------------------------------------------
// stats1 = hits1 ? 1 : stats+1 ; dead1 bitmask = stats1 > 30
// ---------------------------------------------------------------------------
__global__ void k_stats1(const int* __restrict__ stats_in) {
    int h = blockIdx.x * 256 + threadIdx.x;
    int s1 = g_hits1[h] ? 1 : stats_in[h] + 1;
    g_stats1[h] = s1;
    unsigned b = __ballot_sync(0xFFFFFFFFu, s1 > 30);
    if ((threadIdx.x & 31) == 0) g_dead1[h >> 5] = b;
}

// ---------------------------------------------------------------------------
// top-512 & top-256 on pre*dead1: lat_aux, lat_4k, hits2, compact list
// ---------------------------------------------------------------------------
__global__ void k_selaux(float* __restrict__ lataux, float* __restrict__ lat4k) {
    __shared__ SelShared s;
    __shared__ unsigned db[Hn / 32];
    const int r = blockIdx.x, tid = threadIdx.x;
    for (int i = tid; i < Hn / 32; i += 256) db[i] = g_dead1[i];
    if (tid == 0) s.cnt = 0;
    __syncthreads();
    const float* row = g_pre + (size_t)r * Hn;
    for (int i = tid; i < Hn; i += 256) {
        float v  = row[i];
        float mv = ((db[i >> 5] >> (i & 31)) & 1u) ? v : 0.f;
        s.sv[i] = mv;
        s.su[i] = fkey(mv);
    }
    __syncthreads();
    unsigned t512 = radix_kth(&s, 512);
    unsigned t256 = radix_kth(&s, 256);
    float* oa = lataux + (size_t)r * Hn;
    float* o4 = lat4k  + (size_t)r * Hn;
    for (int i = tid; i < Hn; i += 256) {
        float v = s.sv[i];
        unsigned u = s.su[i];
        bool s5 = (u >= t512), s2 = (u >= t256);
        oa[i] = s5 ? fmaxf(v, 0.f) : 0.f;
        o4[i] = s2 ? fmaxf(v, 0.f) : 0.f;
        if (s2 && v > 1e-5f) g_hits2[i] = 1;
        if (s5 && v > 0.f) {
            int p = atomicAdd(&s.cnt, 1);
            if (p < MAXA) {
                g_aidx[(size_t)r * MAXA + p] = i | (s2 ? 0x10000 : 0);
                g_aval[(size_t)r * MAXA + p] = v;
            }
        }
    }
    __syncthreads();
    if (tid == 0) g_acnt[r] = (s.cnt < MAXA) ? s.cnt : MAXA;
}

// ---------------------------------------------------------------------------
// stats2 (output) and combined dead mask
// ---------------------------------------------------------------------------
__global__ void k_stats2(float* __restrict__ out_stats) {
    int h = blockIdx.x * 256 + threadIdx.x;
    int s2 = g_hits2[h] ? 1 : g_stats1[h] + 1;
    out_stats[h] = (float)s2;
    unsigned b = __ballot_sync(0xFFFFFFFFu, s2 > 30);
    if ((threadIdx.x & 31) == 0) g_dead12[h >> 5] = g_dead1[h >> 5] & b;
}

// ---------------------------------------------------------------------------
// pre_m2 = pre * dead1 * dead2
// ---------------------------------------------------------------------------
__global__ void k_prem2(float* __restrict__ out) {
    size_t i4 = (size_t)blockIdx.x * 256 + threadIdx.x;  // over Bn*Hn/4
    int h0 = (int)(i4 & (Hn / 4 - 1)) * 4;
    unsigned w = g_dead12[h0 >> 5];
    float4 p = ((const float4*)g_pre)[i4];
    float4 o;
    o.x = ((w >> ((h0 & 31) + 0)) & 1u) ? p.x : 0.f;
    o.y = ((w >> ((h0 & 31) + 1)) & 1u) ? p.y : 0.f;
    o.z = ((w >> ((h0 & 31) + 2)) & 1u) ? p.z : 0.f;
    o.w = ((w >> ((h0 & 31) + 3)) & 1u) ? p.w : 0.f;
    ((float4*)out)[i4] = o;
}

// ---------------------------------------------------------------------------
// sparse gather decode: recons = lat @ W + pre_bias  (3 decodes, 4 outputs)
// one block per row; thread t owns columns 4t..4t+3
// ---------------------------------------------------------------------------
__global__ void k_decode(const float* __restrict__ W,
                         const float* __restrict__ pb,
                         float* __restrict__ out) {
    __shared__ int   si[MAXK + MAXA];
    __shared__ float sw[MAXK + MAXA];
    const int r = blockIdx.x, tid = threadIdx.x;
    const int ck = g_kcnt[r], ca = g_acnt[r];
    for (int i = tid; i < ck; i += 256) {
        si[i] = g_kidx[(size_t)r * MAXK + i];
        sw[i] = g_kval[(size_t)r * MAXK + i];
    }
    for (int i = tid; i < ca; i += 256) {
        si[MAXK + i] = g_aidx[(size_t)r * MAXA + i];
        sw[MAXK + i] = g_aval[(size_t)r * MAXA + i];
    }
    __syncthreads();

    const int c0 = tid * 4;
    float4 ak = {0, 0, 0, 0}, aa = {0, 0, 0, 0}, a4 = {0, 0, 0, 0};

#pragma unroll 4
    for (int i = 0; i < ck; i++) {
        float v = sw[i];
        float4 w = *(const float4*)(W + (size_t)si[i] * Dn + c0);
        ak.x += v * w.x; ak.y += v * w.y; ak.z += v * w.z; ak.w += v * w.w;
    }
#pragma unroll 4
    for (int i = 0; i < ca; i++) {
        int e = si[MAXK + i];
        float v = sw[MAXK + i];
        int h = e & 0xFFFF;
        float v4 = (e & 0x10000) ? v : 0.f;
        float4 w = *(const float4*)(W + (size_t)h * Dn + c0);
        aa.x += v * w.x;  aa.y += v * w.y;  aa.z += v * w.z;  aa.w += v * w.w;
        a4.x += v4 * w.x; a4.y += v4 * w.y; a4.z += v4 * w.z; a4.w += v4 * w.w;
    }

    float4 b = *(const float4*)(pb + c0);
    float4 rk, r4, ra, rkp;
    rk.x = ak.x + b.x; rk.y = ak.y + b.y; rk.z = ak.z + b.z; rk.w = ak.w + b.w;
    r4.x = a4.x + b.x; r4.y = a4.y + b.y; r4.z = a4.z + b.z; r4.w = a4.w + b.w;
    ra.x = aa.x + b.x; ra.y = aa.y + b.y; ra.z = aa.z + b.z; ra.w = aa.w + b.w;
    // mimic reference: (z@W + pre_bias) - pre_bias (re-subtract the rounded sum)
    rkp.x = rk.x - b.x; rkp.y = rk.y - b.y; rkp.z = rk.z - b.z; rkp.w = rk.w - b.w;

    size_t o = (size_t)r * Dn + c0;
    *(float4*)(out + OFF_RECK   + o) = rk;
    *(float4*)(out + OFF_REC4K  + o) = r4;
    *(float4*)(out + OFF_RECAUX + o) = ra;
    *(float4*)(out + OFF_RECKPB + o) = rkp;
}

// ---------------------------------------------------------------------------
extern "C" void kernel_launch(void* const* d_in, const int* in_sizes, int n_in,
                              void* d_out, int out_size) {
    const float* x     = (const float*)d_in[0];
    const float* pbias = (const float*)d_in[1];
    const float* W     = (const float*)d_in[2];
    const float* lb    = (const float*)d_in[3];
    const int*   stats = (const int*)d_in[4];
    float* out = (float*)d_out;

    k_init<<<(Hn + 255) / 256, 256>>>();
    k_xb<<<(Bn * Dn / 4) / 256, 256>>>(x, pbias, out + OFF_XB);

    dim3 gg(Hn / BN, Bn / BM);
    k_gemm<<<gg, 256>>>(out + OFF_XB, W, lb);

    k_sel64<<<Bn, 256>>>(out + OFF_LATK);
    k_stats1<<<Hn / 256, 256>>>(stats);
    k_selaux<<<Bn, 256>>>(out + OFF_LATAUX, out + OFF_LAT4K);
    k_stats2<<<Hn / 256, 256>>>(out + OFF_STATS);
    k_prem2<<<(int)(((size_t)Bn * Hn / 4) / 256), 256>>>(out + OFF_PREM2);
    k_decode<<<Bn, 256>>>(W, pbias, out);
}